// round 3
// baseline (speedup 1.0000x reference)
#include <cuda_runtime.h>

#define BATCH 32
#define CCH   256
#define HW    1024
#define TILE  128
#define KT    16
#define INV_T 14.285714285714286f   // 1 / 0.07

// ---------------- scratch (static device globals: no allocation) ----------------
__device__ float    g_At[(size_t)BATCH * CCH * HW];     // 32 MB : A transposed (w,h)->j
__device__ float    g_M [(size_t)BATCH * HW * HW];      // 128 MB: G[b][j][i] = M[b][i][j]/T
__device__ unsigned g_maxIk[BATCH * HW];                // ordered-uint keys of maxI[i]
__device__ unsigned g_maxJk[BATCH * HW];                // ordered-uint keys of maxJ[j]
__device__ float    g_sumI[BATCH * HW];
__device__ float    g_sumJ[BATCH * HW];

// ---------------- helpers ----------------
__device__ __forceinline__ unsigned fkey(float f) {
    unsigned u = __float_as_uint(f);
    return u ^ ((unsigned)(((int)u) >> 31) | 0x80000000u);  // monotone float->uint
}
__device__ __forceinline__ float kdec(unsigned k) {
    unsigned u = (k & 0x80000000u) ? (k ^ 0x80000000u) : ~k;
    return __uint_as_float(u);
}

// packed 2xFP32 FMA (Blackwell f32x2 pipe; 2 FMA per lane-instr)
__device__ __forceinline__ void fma2(unsigned long long& d, unsigned long long a,
                                     unsigned long long b) {
    asm("fma.rn.f32x2 %0, %1, %2, %0;" : "+l"(d) : "l"(a), "l"(b));
}
__device__ __forceinline__ unsigned long long pack2(float x, float y) {
    unsigned long long r;
    asm("mov.b64 %0, {%1, %2};" : "=l"(r) : "f"(x), "f"(y));
    return r;
}
__device__ __forceinline__ float2 unpack2(unsigned long long v) {
    float2 f;
    asm("mov.b64 {%0, %1}, %2;" : "=f"(f.x), "=f"(f.y) : "l"(v));
    return f;
}

// ---------------- K0a: reset stats (must run every graph replay) ----------------
__global__ void k_init() {
    int idx = blockIdx.x * blockDim.x + threadIdx.x;
    if (idx < BATCH * HW) {
        g_maxIk[idx] = 0u;   // below fkey of any real value
        g_maxJk[idx] = 0u;
        g_sumI[idx]  = 0.f;
        g_sumJ[idx]  = 0.f;
    }
}

// ---------------- K0b: A_flat[b][c][j] = A[b][c][j%32][j/32] ----------------
__global__ __launch_bounds__(256) void k_transpose(const float* __restrict__ A) {
    __shared__ float s[32][33];
    const size_t plane = blockIdx.x;  // b*C + c
    const float* Ap = A + plane * 1024;
    float*       Op = g_At + plane * 1024;
    const int t = threadIdx.x;
#pragma unroll
    for (int l = 0; l < 4; l++) {
        int idx = t + l * 256;
        s[idx >> 5][idx & 31] = Ap[idx];
    }
    __syncthreads();
#pragma unroll
    for (int l = 0; l < 4; l++) {
        int idx = t + l * 256;
        Op[idx] = s[idx & 31][idx >> 5];   // At[j] = A[h=j%32][w=j/32]
    }
}

// ---------------- K1: G[b][j][i] = (1/T) * sum_c At[c][j]*B[c][i]  + maxes ------
__global__ __launch_bounds__(256, 2) void k_gemm(const float* __restrict__ Bf) {
    __shared__ float sA[KT][TILE];
    __shared__ float sB[KT][TILE];
    __shared__ float red[16][TILE];

    const int b  = blockIdx.z;
    const int i0 = blockIdx.x * TILE;
    const int j0 = blockIdx.y * TILE;
    const float* __restrict__ Bp = Bf   + (size_t)b * CCH * HW;  // [c][i]
    const float* __restrict__ Ap = g_At + (size_t)b * CCH * HW;  // [c][j]

    const int t  = threadIdx.x;
    const int tx = t & 15, ty = t >> 4;
    const int ldk = t >> 5;          // 0..7
    const int ldc = (t & 31) << 2;   // 0,4,...,124

    unsigned long long acc[8][4];
#pragma unroll
    for (int j = 0; j < 8; j++)
#pragma unroll
        for (int q = 0; q < 4; q++) acc[j][q] = 0ULL;

    // prefetch first K-slice
    float4 pa0 = *(const float4*)(Ap + (size_t)ldk * HW + j0 + ldc);
    float4 pa1 = *(const float4*)(Ap + (size_t)(ldk + 8) * HW + j0 + ldc);
    float4 pb0 = *(const float4*)(Bp + (size_t)ldk * HW + i0 + ldc);
    float4 pb1 = *(const float4*)(Bp + (size_t)(ldk + 8) * HW + i0 + ldc);

    for (int k0 = 0; k0 < CCH; k0 += KT) {
        __syncthreads();
        *(float4*)&sA[ldk][ldc]     = pa0;
        *(float4*)&sA[ldk + 8][ldc] = pa1;
        *(float4*)&sB[ldk][ldc]     = pb0;
        *(float4*)&sB[ldk + 8][ldc] = pb1;
        __syncthreads();
        if (k0 + KT < CCH) {
            const int kn = k0 + KT;
            pa0 = *(const float4*)(Ap + (size_t)(kn + ldk) * HW + j0 + ldc);
            pa1 = *(const float4*)(Ap + (size_t)(kn + ldk + 8) * HW + j0 + ldc);
            pb0 = *(const float4*)(Bp + (size_t)(kn + ldk) * HW + i0 + ldc);
            pb1 = *(const float4*)(Bp + (size_t)(kn + ldk + 8) * HW + i0 + ldc);
        }
#pragma unroll
        for (int kk = 0; kk < KT; kk++) {
            // B pairs loaded directly as 64-bit packed operands
            ulonglong2 u0 = *(const ulonglong2*)&sB[kk][tx << 2];
            ulonglong2 u1 = *(const ulonglong2*)&sB[kk][64 + (tx << 2)];
            unsigned long long bp[4] = {u0.x, u0.y, u1.x, u1.y};
            float4 aA = *(const float4*)&sA[kk][ty << 2];
            float4 aB = *(const float4*)&sA[kk][64 + (ty << 2)];
            float aj[8] = {aA.x, aA.y, aA.z, aA.w, aB.x, aB.y, aB.z, aB.w};
#pragma unroll
            for (int j = 0; j < 8; j++) {
                unsigned long long a2 = pack2(aj[j], aj[j]);
#pragma unroll
                for (int q = 0; q < 4; q++) fma2(acc[j][q], a2, bp[q]);
            }
        }
    }

    // unpack accumulators, apply 1/TEMPERATURE
    float av[8][8];
#pragma unroll
    for (int j = 0; j < 8; j++)
#pragma unroll
        for (int q = 0; q < 4; q++) {
            float2 f = unpack2(acc[j][q]);
            av[j][2 * q]     = f.x * INV_T;
            av[j][2 * q + 1] = f.y * INV_T;
        }

    // store G (coalesced float4 per 16-lane group)
#pragma unroll
    for (int j = 0; j < 8; j++) {
        const int jl = (j < 4) ? (ty * 4 + j) : (64 + ty * 4 + (j - 4));
        float* row = g_M + ((size_t)b * HW + j0 + jl) * HW + i0;
        *(float4*)(row + (tx << 2))      = make_float4(av[j][0], av[j][1], av[j][2], av[j][3]);
        *(float4*)(row + 64 + (tx << 2)) = make_float4(av[j][4], av[j][5], av[j][6], av[j][7]);
    }

    // per-thread maxes over micro-tile
    float mi[8], mj[8];
#pragma unroll
    for (int ii = 0; ii < 8; ii++) {
        float m = av[0][ii];
#pragma unroll
        for (int j = 1; j < 8; j++) m = fmaxf(m, av[j][ii]);
        mi[ii] = m;
    }
#pragma unroll
    for (int j = 0; j < 8; j++) {
        float m = av[j][0];
#pragma unroll
        for (int ii = 1; ii < 8; ii++) m = fmaxf(m, av[j][ii]);
        mj[j] = m;
    }

    // reduce maxI over j within tile, then global atomicMax
    __syncthreads();
#pragma unroll
    for (int idx = 0; idx < 8; idx++) {
        const int il = (idx < 4) ? (tx * 4 + idx) : (64 + tx * 4 + (idx - 4));
        red[ty][il] = mi[idx];
    }
    __syncthreads();
    if (t < TILE) {
        float m = red[0][t];
#pragma unroll
        for (int r = 1; r < 16; r++) m = fmaxf(m, red[r][t]);
        atomicMax(&g_maxIk[b * HW + i0 + t], fkey(m));
    }
    __syncthreads();
#pragma unroll
    for (int j = 0; j < 8; j++) {
        const int jl = (j < 4) ? (ty * 4 + j) : (64 + ty * 4 + (j - 4));
        red[tx][jl] = mj[j];
    }
    __syncthreads();
    if (t < TILE) {
        float m = red[0][t];
#pragma unroll
        for (int r = 1; r < 16; r++) m = fmaxf(m, red[r][t]);
        atomicMax(&g_maxJk[b * HW + j0 + t], fkey(m));
    }
}

// ---------------- K2: fused exp-sum stats (one pass over G) ----------------
__global__ __launch_bounds__(256) void k_stats() {
    __shared__ float mI[TILE], mJ[TILE], sJ[TILE], sIa[256];
    const int b = blockIdx.z, i0 = blockIdx.x * TILE, j0 = blockIdx.y * TILE;
    const int t = threadIdx.x;
    if (t < TILE) {
        mI[t] = kdec(g_maxIk[b * HW + i0 + t]);
        mJ[t] = kdec(g_maxJk[b * HW + j0 + t]);
        sJ[t] = 0.f;
    }
    __syncthreads();
    const int ii = t & 127, half = t >> 7;
    const float* Gp = g_M + ((size_t)b * HW + j0) * HW + i0;
    const float mIi = mI[ii];
    float accI = 0.f;
#pragma unroll 4
    for (int jj = half; jj < TILE; jj += 2) {
        float g = Gp[(size_t)jj * HW + ii];
        accI += __expf(g - mIi);
        float e2 = __expf(g - mJ[jj]);
#pragma unroll
        for (int off = 16; off > 0; off >>= 1) e2 += __shfl_xor_sync(0xffffffffu, e2, off);
        if ((t & 31) == 0) atomicAdd(&sJ[jj], e2);
    }
    sIa[t] = accI;
    __syncthreads();
    if (t < TILE) {
        atomicAdd(&g_sumI[b * HW + i0 + t], sIa[t] + sIa[t + TILE]);
        atomicAdd(&g_sumJ[b * HW + j0 + t], sJ[t]);
    }
}

// ---------------- K3: out[b][j][i] = exp(2G - mI - mJ)/(sI*sJ) ----------------
__global__ __launch_bounds__(256) void k_final(float* __restrict__ out) {
    __shared__ float mI[TILE], mJ[TILE], rI[TILE], rJ[TILE];
    const int b = blockIdx.z, i0 = blockIdx.x * TILE, j0 = blockIdx.y * TILE;
    const int t = threadIdx.x;
    if (t < TILE) {
        mI[t] = kdec(g_maxIk[b * HW + i0 + t]);
        mJ[t] = kdec(g_maxJk[b * HW + j0 + t]);
        rI[t] = 1.0f / g_sumI[b * HW + i0 + t];
        rJ[t] = 1.0f / g_sumJ[b * HW + j0 + t];
    }
    __syncthreads();
    const float* Gp = g_M + ((size_t)b * HW + j0) * HW + i0;
    float*       Op = out + ((size_t)b * HW + j0) * HW + i0;
#pragma unroll 4
    for (int idx = t; idx < TILE * TILE; idx += 256) {
        const int jj = idx >> 7, ii = idx & 127;
        float g = Gp[(size_t)jj * HW + ii];
        Op[(size_t)jj * HW + ii] =
            __expf(2.f * g - mI[ii] - mJ[jj]) * rI[ii] * rJ[jj];
    }
}

// ---------------- launch ----------------
extern "C" void kernel_launch(void* const* d_in, const int* in_sizes, int n_in,
                              void* d_out, int out_size) {
    const float* A  = (const float*)d_in[0];
    const float* Bf = (const float*)d_in[1];
    float* out = (float*)d_out;

    k_init<<<(BATCH * HW + 255) / 256, 256>>>();
    k_transpose<<<BATCH * CCH, 256>>>(A);
    dim3 grid(HW / TILE, HW / TILE, BATCH);
    k_gemm<<<grid, 256>>>(Bf);
    k_stats<<<grid, 256>>>();
    k_final<<<grid, 256>>>(out);
}

// round 6
// speedup vs baseline: 1.1818x; 1.1818x over previous
#include <cuda_runtime.h>
#include <cstdint>

#define BATCH 32
#define CCH   256
#define HW    1024
#define TM 128
#define TN 128
#define KT 16
#define RS 136                       // smem row stride (floats): conflict-free frags
#define ABYTES (KT * RS * 4)         // 8704 B per operand array
#define BUFB   (4 * ABYTES)          // 34816 B per buffer (Ah, Al, Bh, Bl)
#define SMEM_DYN (2 * BUFB)
#define INV_T 14.285714285714286f

__device__ float    g_Ah[(size_t)BATCH * CCH * HW];
__device__ float    g_Al[(size_t)BATCH * CCH * HW];
__device__ float    g_Bh[(size_t)BATCH * CCH * HW];
__device__ float    g_Bl[(size_t)BATCH * CCH * HW];
__device__ float    g_M [(size_t)BATCH * HW * HW];
__device__ unsigned g_maxIk[BATCH * HW];
__device__ unsigned g_maxJk[BATCH * HW];
__device__ float    g_sumI[BATCH * HW];
__device__ float    g_sumJ[BATCH * HW];

__device__ __forceinline__ unsigned fkey(float f) {
    unsigned u = __float_as_uint(f);
    return u ^ ((unsigned)(((int)u) >> 31) | 0x80000000u);
}
__device__ __forceinline__ float kdec(unsigned k) {
    unsigned u = (k & 0x80000000u) ? (k ^ 0x80000000u) : ~k;
    return __uint_as_float(u);
}
__device__ __forceinline__ uint32_t smem_u32(const void* p) {
    uint32_t a;
    asm("{ .reg .u64 t; cvta.to.shared.u64 t, %1; cvt.u32.u64 %0, t; }" : "=r"(a) : "l"(p));
    return a;
}
__device__ __forceinline__ void tf32_split(float v, float& hi, float& lo) {
    uint32_t hv; asm("cvt.rna.tf32.f32 %0, %1;" : "=r"(hv) : "f"(v));
    hi = __uint_as_float(hv);
    float r = v - hi;
    uint32_t lv; asm("cvt.rna.tf32.f32 %0, %1;" : "=r"(lv) : "f"(r));
    lo = __uint_as_float(lv);
}
__device__ __forceinline__ void cp16(uint32_t dst, const float* src) {
    asm volatile("cp.async.cg.shared.global [%0], [%1], 16;" :: "r"(dst), "l"(src));
}
#define CP_COMMIT() asm volatile("cp.async.commit_group;" ::: "memory")
#define CP_WAIT1()  asm volatile("cp.async.wait_group 1;" ::: "memory")

__device__ __forceinline__ void mma8(float* c, const unsigned* a, const unsigned* b) {
    asm volatile(
        "mma.sync.aligned.m16n8k8.row.col.f32.tf32.tf32.f32 "
        "{%0,%1,%2,%3}, {%4,%5,%6,%7}, {%8,%9}, {%0,%1,%2,%3};"
        : "+f"(c[0]), "+f"(c[1]), "+f"(c[2]), "+f"(c[3])
        : "r"(a[0]), "r"(a[1]), "r"(a[2]), "r"(a[3]), "r"(b[0]), "r"(b[1]));
}

// ---------------- K0: reset (sumI accumulated, maxes via atomicMax) ----------------
__global__ void k_init() {
    int idx = blockIdx.x * blockDim.x + threadIdx.x;
    if (idx < BATCH * HW) {
        g_maxIk[idx] = 0u;
        g_maxJk[idx] = 0u;
        g_sumI[idx]  = 0.f;
    }
}

// ---------------- K1: transpose A (h,w)->(j=w*32+h) fused with tf32 split ----------
__global__ __launch_bounds__(256) void k_transA(const float* __restrict__ A) {
    __shared__ float s[32][33];
    const size_t plane = blockIdx.x;                 // b*C + c
    const float* Ap = A + plane * 1024;
    float* Oh = g_Ah + plane * 1024;
    float* Ol = g_Al + plane * 1024;
    const int t = threadIdx.x;
#pragma unroll
    for (int l = 0; l < 4; l++) { int idx = t + l * 256; s[idx >> 5][idx & 31] = Ap[idx]; }
    __syncthreads();
#pragma unroll
    for (int l = 0; l < 4; l++) {
        int idx = t + l * 256;
        float hi, lo;
        tf32_split(s[idx & 31][idx >> 5], hi, lo);
        Oh[idx] = hi; Ol[idx] = lo;
    }
}

// ---------------- K2: elementwise tf32 split of B ----------------
__global__ __launch_bounds__(256) void k_splitB(const float* __restrict__ B) {
    size_t idx = ((size_t)blockIdx.x * 256 + threadIdx.x) * 4;
    float4 v = *(const float4*)(B + idx);
    float4 h, l;
    tf32_split(v.x, h.x, l.x); tf32_split(v.y, h.y, l.y);
    tf32_split(v.z, h.z, l.z); tf32_split(v.w, h.w, l.w);
    *(float4*)(g_Bh + idx) = h;
    *(float4*)(g_Bl + idx) = l;
}

// ---------------- K3: mma.sync tf32 3-split GEMM + tile maxes ----------------
__device__ __forceinline__ void fill_buf(uint32_t buf, int k0,
                                         const float* pAh, const float* pAl,
                                         const float* pBh, const float* pBl, int t) {
#pragma unroll
    for (int l = 0; l < 2; l++) {
        int f4 = t + 256 * l;
        int r = f4 >> 5, c4 = f4 & 31;
        uint32_t so = (uint32_t)(r * RS + c4 * 4) * 4u;
        size_t go = (size_t)(k0 + r) * HW + c4 * 4;
        cp16(buf + 0 * ABYTES + so, pAh + go);
        cp16(buf + 1 * ABYTES + so, pAl + go);
        cp16(buf + 2 * ABYTES + so, pBh + go);
        cp16(buf + 3 * ABYTES + so, pBl + go);
    }
}

__global__ __launch_bounds__(256) void k_gemm_mma() {
    extern __shared__ float dsm[];
    __shared__ unsigned rowk[TM], colk[TN];
    const uint32_t sb = smem_u32(dsm);

    const int t = threadIdx.x;
    const int b = blockIdx.z, i0 = blockIdx.x * TN, j0 = blockIdx.y * TM;
    const int wid = t >> 5, lane = t & 31;
    const int wm = wid >> 1, wn = wid & 1;           // 4 x 2 warps
    const int g = lane >> 2, tig = lane & 3;

    if (t < TM) rowk[t] = 0u;
    if (t < TN) colk[t] = 0u;

    const float* pAh = g_Ah + (size_t)b * CCH * HW + j0;
    const float* pAl = g_Al + (size_t)b * CCH * HW + j0;
    const float* pBh = g_Bh + (size_t)b * CCH * HW + i0;
    const float* pBl = g_Bl + (size_t)b * CCH * HW + i0;

    float c[2][8][4];
#pragma unroll
    for (int mt = 0; mt < 2; mt++)
#pragma unroll
        for (int nt = 0; nt < 8; nt++)
#pragma unroll
            for (int q = 0; q < 4; q++) c[mt][nt][q] = 0.f;

    fill_buf(sb, 0, pAh, pAl, pBh, pBl, t);
    CP_COMMIT();
    fill_buf(sb + BUFB, KT, pAh, pAl, pBh, pBl, t);
    CP_COMMIT();

    for (int k = 0; k < CCH / KT; k++) {
        const int p = k & 1;
        const float* s0 = dsm + p * (BUFB / 4);
        const float* sAh = s0;
        const float* sAl = s0 + ABYTES / 4;
        const float* sBh = s0 + 2 * (ABYTES / 4);
        const float* sBl = s0 + 3 * (ABYTES / 4);
        CP_WAIT1();
        __syncthreads();
#pragma unroll
        for (int kk = 0; kk < KT; kk += 8) {
            unsigned ah[2][4], al[2][4], bh[8][2], bl[8][2];
#pragma unroll
            for (int mt = 0; mt < 2; mt++) {
                const int m = wm * 32 + mt * 16 + g;
                ah[mt][0] = __float_as_uint(sAh[(kk + tig) * RS + m]);
                ah[mt][1] = __float_as_uint(sAh[(kk + tig) * RS + m + 8]);
                ah[mt][2] = __float_as_uint(sAh[(kk + tig + 4) * RS + m]);
                ah[mt][3] = __float_as_uint(sAh[(kk + tig + 4) * RS + m + 8]);
                al[mt][0] = __float_as_uint(sAl[(kk + tig) * RS + m]);
                al[mt][1] = __float_as_uint(sAl[(kk + tig) * RS + m + 8]);
                al[mt][2] = __float_as_uint(sAl[(kk + tig + 4) * RS + m]);
                al[mt][3] = __float_as_uint(sAl[(kk + tig + 4) * RS + m + 8]);
            }
#pragma unroll
            for (int nt = 0; nt < 8; nt++) {
                const int n = wn * 64 + nt * 8 + g;
                bh[nt][0] = __float_as_uint(sBh[(kk + tig) * RS + n]);
                bh[nt][1] = __float_as_uint(sBh[(kk + tig + 4) * RS + n]);
                bl[nt][0] = __float_as_uint(sBl[(kk + tig) * RS + n]);
                bl[nt][1] = __float_as_uint(sBl[(kk + tig + 4) * RS + n]);
            }
#pragma unroll
            for (int mt = 0; mt < 2; mt++)
#pragma unroll
                for (int nt = 0; nt < 8; nt++) {
                    mma8(c[mt][nt], ah[mt], bh[nt]);
                    mma8(c[mt][nt], ah[mt], bl[nt]);
                    mma8(c[mt][nt], al[mt], bh[nt]);
                }
        }
        __syncthreads();
        if (k + 2 < CCH / KT)
            fill_buf(sb + p * BUFB, (k + 2) * KT, pAh, pAl, pBh, pBl, t);
        CP_COMMIT();
    }

    // scale
#pragma unroll
    for (int mt = 0; mt < 2; mt++)
#pragma unroll
        for (int nt = 0; nt < 8; nt++)
#pragma unroll
            for (int q = 0; q < 4; q++) c[mt][nt][q] *= INV_T;

    // store G: float2 per (mt, hb, nt)
#pragma unroll
    for (int mt = 0; mt < 2; mt++)
#pragma unroll
        for (int hb = 0; hb < 2; hb++) {
            const int j = j0 + wm * 32 + mt * 16 + g + 8 * hb;
            float* rowp = g_M + ((size_t)b * HW + j) * HW + i0 + wn * 64;
#pragma unroll
            for (int nt = 0; nt < 8; nt++)
                *(float2*)(rowp + nt * 8 + tig * 2) =
                    make_float2(c[mt][nt][2 * hb], c[mt][nt][2 * hb + 1]);
        }

    // row maxes (reduce across tig quad)
#pragma unroll
    for (int mt = 0; mt < 2; mt++)
#pragma unroll
        for (int hb = 0; hb < 2; hb++) {
            float m = -3.0e38f;
#pragma unroll
            for (int nt = 0; nt < 8; nt++)
                m = fmaxf(m, fmaxf(c[mt][nt][2 * hb], c[mt][nt][2 * hb + 1]));
#pragma unroll
            for (int o = 1; o < 4; o <<= 1)
                m = fmaxf(m, __shfl_xor_sync(0xffffffffu, m, o));
            if (tig == 0) atomicMax(&rowk[wm * 32 + mt * 16 + g + 8 * hb], fkey(m));
        }
    // col maxes (reduce across g: lanes stride 4)
#pragma unroll
    for (int nt = 0; nt < 8; nt++)
#pragma unroll
        for (int par = 0; par < 2; par++) {
            float m = fmaxf(fmaxf(c[0][nt][par], c[0][nt][2 + par]),
                            fmaxf(c[1][nt][par], c[1][nt][2 + par]));
#pragma unroll
            for (int o = 4; o < 32; o <<= 1)
                m = fmaxf(m, __shfl_xor_sync(0xffffffffu, m, o));
            if (g == 0) atomicMax(&colk[wn * 64 + nt * 8 + tig * 2 + par], fkey(m));
        }
    __syncthreads();
    if (t < TM) atomicMax(&g_maxJk[b * HW + j0 + t], rowk[t]);
    if (t < TN) atomicMax(&g_maxIk[b * HW + i0 + t], colk[t]);
}

// ---------------- K4: stats — CTA covers 128 rows x ALL cols ----------------
__global__ __launch_bounds__(256) void k_stats() {
    __shared__ float sI[8][1024];
    const int b = blockIdx.y, j0 = blockIdx.x * 128;
    const int t = threadIdx.x, w = t >> 5, lane = t & 31;

    float mIv[32], accI[32];
#pragma unroll
    for (int q = 0; q < 8; q++)
#pragma unroll
        for (int s = 0; s < 4; s++) {
            mIv[q * 4 + s] = kdec(g_maxIk[b * HW + q * 128 + lane * 4 + s]);
            accI[q * 4 + s] = 0.f;
        }

    for (int r = 0; r < 16; r++) {
        const int row = j0 + w + 8 * r;
        const float mJ = kdec(g_maxJk[b * HW + row]);
        const float* Gp = g_M + ((size_t)b * HW + row) * HW;
        float accJ = 0.f;
#pragma unroll
        for (int q = 0; q < 8; q++) {
            float4 v = *(const float4*)(Gp + q * 128 + lane * 4);
            accJ += __expf(v.x - mJ) + __expf(v.y - mJ) +
                    __expf(v.z - mJ) + __expf(v.w - mJ);
            accI[q * 4 + 0] += __expf(v.x - mIv[q * 4 + 0]);
            accI[q * 4 + 1] += __expf(v.y - mIv[q * 4 + 1]);
            accI[q * 4 + 2] += __expf(v.z - mIv[q * 4 + 2]);
            accI[q * 4 + 3] += __expf(v.w - mIv[q * 4 + 3]);
        }
#pragma unroll
        for (int o = 16; o > 0; o >>= 1) accJ += __shfl_xor_sync(0xffffffffu, accJ, o);
        if (lane == 0) g_sumJ[b * HW + row] = accJ;   // full row in one CTA: plain store
    }
#pragma unroll
    for (int q = 0; q < 8; q++)
#pragma unroll
        for (int s = 0; s < 4; s++) sI[w][q * 128 + lane * 4 + s] = accI[q * 4 + s];
    __syncthreads();
#pragma unroll
    for (int col = t; col < 1024; col += 256) {
        float s = 0.f;
#pragma unroll
        for (int ww = 0; ww < 8; ww++) s += sI[ww][col];
        atomicAdd(&g_sumI[b * HW + col], s);
    }
}

// ---------------- K5: out = exp(2G - mI - mJ) / (sI*sJ) ----------------
__global__ __launch_bounds__(256) void k_final(float* __restrict__ out) {
    __shared__ float mI[128], mJ[128], rI[128], rJ[128];
    const int b = blockIdx.z, i0 = blockIdx.x * 128, j0 = blockIdx.y * 128;
    const int t = threadIdx.x;
    if (t < 128) {
        mI[t] = kdec(g_maxIk[b * HW + i0 + t]);
        mJ[t] = kdec(g_maxJk[b * HW + j0 + t]);
        rI[t] = 1.0f / g_sumI[b * HW + i0 + t];
        rJ[t] = 1.0f / g_sumJ[b * HW + j0 + t];
    }
    __syncthreads();
    const float* Gp = g_M + ((size_t)b * HW + j0) * HW + i0;
    float*       Op = out + ((size_t)b * HW + j0) * HW + i0;
#pragma unroll 4
    for (int idx = t; idx < 128 * 128; idx += 256) {
        const int jj = idx >> 7, ii = idx & 127;
        float gv = Gp[(size_t)jj * HW + ii];
        Op[(size_t)jj * HW + ii] = __expf(2.f * gv - mI[ii] - mJ[jj]) * rI[ii] * rJ[jj];
    }
}

// ---------------- launch ----------------
extern "C" void kernel_launch(void* const* d_in, const int* in_sizes, int n_in,
                              void* d_out, int out_size) {
    const float* A  = (const float*)d_in[0];
    const float* Bf = (const float*)d_in[1];
    float* out = (float*)d_out;

    cudaFuncSetAttribute(k_gemm_mma, cudaFuncAttributeMaxDynamicSharedMemorySize, SMEM_DYN);

    k_init<<<(BATCH * HW + 255) / 256, 256>>>();
    k_transA<<<BATCH * CCH, 256>>>(A);
    k_splitB<<<(BATCH * CCH * HW) / 1024, 256>>>(Bf);
    dim3 ggrid(HW / TN, HW / TM, BATCH);
    k_gemm_mma<<<ggrid, 256, SMEM_DYN>>>();
    dim3 sgrid(HW / 128, BATCH);
    k_stats<<<sgrid, 256>>>();
    dim3 fgrid(HW / 128, HW / 128, BATCH);
    k_final<<<fgrid, 256>>>(out);
}